// round 5
// baseline (speedup 1.0000x reference)
#include <cuda_runtime.h>
#include <math.h>

// Problem constants (fixed by the dataset)
#define NN 8192          // atoms
#define NB 32            // graphs
#define NH 64            // hidden
#define NK 729           // 9^3 lattice points (k=0 kept with w=0)

#define TWO_PI  6.28318530717958647692f
#define FOUR_PI 12.5663706143591729539f

// -------- device scratch (no allocations allowed) --------
__device__ float g_inv[NB][9];      // inverse cells, row-major [d][h]
__device__ float g_vinv[NB];        // 1 / max(|det|, 1e-6)
__device__ int   g_off[NB + 1];     // batch segment offsets (batch is sorted)
__device__ float g_w[NB][NK];       // per-(graph,k) radial weight
// per-atom phasor table: row = (d*9 + (m+4))*2 + {re,im}, col = atom (coalesced)
__device__ float g_phas[54][NN];

// ---------------------------------------------------------------------------
// Kernel 0: 3x3 inverses (double precision) + volumes + batch offsets
// ---------------------------------------------------------------------------
__global__ void k_setup(const float* __restrict__ cell, const int* __restrict__ batch)
{
    int t = threadIdx.x;
    if (t < NB) {
        const float* c = cell + t * 9;
        double a = c[0], b = c[1], cc = c[2];
        double d = c[3], e = c[4], f  = c[5];
        double g = c[6], h = c[7], i  = c[8];
        double A  = e * i - f * h;
        double Bv = f * g - d * i;
        double C  = d * h - e * g;
        double det = a * A + b * Bv + cc * C;
        double vol = fabs(det);
        if (vol < 1e-6) vol = 1e-6;
        g_vinv[t] = (float)(1.0 / vol);
        double id = 1.0 / det;
        g_inv[t][0] = (float)(A * id);
        g_inv[t][1] = (float)((cc * h - b * i) * id);
        g_inv[t][2] = (float)((b * f - cc * e) * id);
        g_inv[t][3] = (float)(Bv * id);
        g_inv[t][4] = (float)((a * i - cc * g) * id);
        g_inv[t][5] = (float)((cc * d - a * f) * id);
        g_inv[t][6] = (float)(C * id);
        g_inv[t][7] = (float)((b * g - a * h) * id);
        g_inv[t][8] = (float)((a * e - b * d) * id);
    }
    if (t <= NB) {   // lower_bound(batch, t) — batch is sorted
        int lo = 0, hi = NN;
        while (lo < hi) {
            int mid = (lo + hi) >> 1;
            if (batch[mid] < t) lo = mid + 1; else hi = mid;
        }
        g_off[t] = lo;
    }
}

// ---------------------------------------------------------------------------
// Kernel 1: per-atom unit phasors e^{i*2pi*frac_d*m}, m=-4..4, d=0..2.
// Only 3 sincos per atom; powers built by complex multiplication.
// Also zero-initializes the (poisoned) output buffer.
// ---------------------------------------------------------------------------
__global__ void k_phasors(const float* __restrict__ pos, const int* __restrict__ batch,
                          float* __restrict__ out)
{
    int n = blockIdx.x * blockDim.x + threadIdx.x;
    if (n >= NN) return;
    out[n] = 0.0f;
    int b = batch[n];
    float px = pos[3 * n], py = pos[3 * n + 1], pz = pos[3 * n + 2];
    #pragma unroll
    for (int d = 0; d < 3; d++) {
        // frac[d] = sum_i pos[i] * inv[i][d]
        float fr = px * g_inv[b][d] + py * g_inv[b][3 + d] + pz * g_inv[b][6 + d];
        float th = TWO_PI * fr;
        float s, c;
        sincosf(th, &s, &c);
        float re[9], im[9];
        re[4] = 1.0f; im[4] = 0.0f;
        re[5] = c;    im[5] = s;
        #pragma unroll
        for (int m = 2; m <= 4; m++) {
            re[4 + m] = re[3 + m] * c - im[3 + m] * s;
            im[4 + m] = re[3 + m] * s + im[3 + m] * c;
        }
        #pragma unroll
        for (int m = 1; m <= 4; m++) { re[4 - m] = re[4 + m]; im[4 - m] = -im[4 + m]; }
        #pragma unroll
        for (int mi = 0; mi < 9; mi++) {
            g_phas[(d * 9 + mi) * 2 + 0][n] = re[mi];
            g_phas[(d * 9 + mi) * 2 + 1][n] = im[mi];
        }
    }
}

// ---------------------------------------------------------------------------
// Kernel 2: MLP radial filter -> g_w[b][k].  One thread per (b,k).
// W2 staged transposed in shared so the inner dot is contiguous.
// ---------------------------------------------------------------------------
__global__ void __launch_bounds__(128) k_weights(
    const float* __restrict__ W1, const float* __restrict__ B1,
    const float* __restrict__ W2, const float* __restrict__ B2,
    const float* __restrict__ W3, const float* __restrict__ B3)
{
    __shared__ float sW1[3 * NH], sB1[NH], sW2T[NH * NH], sB2[NH], sW3[NH];
    __shared__ float sInv[NB * 9];
    int tid = threadIdx.x;
    for (int idx = tid; idx < 3 * NH; idx += blockDim.x) sW1[idx] = W1[idx];
    for (int idx = tid; idx < NH; idx += blockDim.x) {
        sB1[idx] = B1[idx]; sB2[idx] = B2[idx]; sW3[idx] = W3[idx];
    }
    for (int idx = tid; idx < NH * NH; idx += blockDim.x) {
        int i = idx >> 6, j = idx & 63;
        sW2T[j * NH + i] = W2[idx];
    }
    for (int idx = tid; idx < NB * 9; idx += blockDim.x)
        sInv[idx] = (&g_inv[0][0])[idx];
    __syncthreads();

    int g = blockIdx.x * blockDim.x + tid;
    if (g >= NB * NK) return;
    int b = g / NK, k = g - b * NK;
    int ki = k / 81 - 4;
    int kj = (k / 9) % 9 - 4;
    int kk = k % 9 - 4;
    const float* iv = &sInv[b * 9];
    // k_cart[h] = 2pi * sum_d klat[d] * inv[d][h]
    float kc0 = TWO_PI * ((float)ki * iv[0] + (float)kj * iv[3] + (float)kk * iv[6]);
    float kc1 = TWO_PI * ((float)ki * iv[1] + (float)kj * iv[4] + (float)kk * iv[7]);
    float kc2 = TWO_PI * ((float)ki * iv[2] + (float)kj * iv[5] + (float)kk * iv[8]);
    float kn = sqrtf(kc0 * kc0 + kc1 * kc1 + kc2 * kc2);

    float w = 0.0f;
    if (kn > 1e-6f) {           // only k=0 fails this
        float x0 = log1pf(kn);
        float f0 = x0, f1 = x0 * x0, f2 = 1.0f / kn;
        float h1[NH];
        #pragma unroll
        for (int j = 0; j < NH; j++) {
            float a = fmaf(f0, sW1[j], fmaf(f1, sW1[NH + j], fmaf(f2, sW1[2 * NH + j], sB1[j])));
            h1[j] = a / (1.0f + __expf(-a));          // silu
        }
        float o = B3[0];
        for (int j = 0; j < NH; j++) {
            float a = sB2[j];
            #pragma unroll
            for (int i2 = 0; i2 < NH; i2++) a = fmaf(h1[i2], sW2T[j * NH + i2], a);
            float h2 = a / (1.0f + __expf(-a));        // silu
            o = fmaf(h2, sW3[j], o);
        }
        float sp = (o > 80.0f) ? o : log1pf(__expf(o));  // softplus
        w = (FOUR_PI / (kn * kn)) * sp;
    }
    g_w[b][k] = w;
}

// ---------------------------------------------------------------------------
// Kernel 3 (fused): warp owns (graph b, line (i,j)) -> 9 k's.
// Pass 1: accumulate S_cos/S_sin[9][4] over the graph's atoms (lane-strided),
//         butterfly reduce so every lane holds the totals.
// Pass 2: re-walk atoms (L1-hot), compute the 9-k energy contribution per atom,
//         atomicAdd into out[n].
// ---------------------------------------------------------------------------
__global__ void __launch_bounds__(256) k_main(const float* __restrict__ source,
                                              float* __restrict__ out)
{
    int b    = blockIdx.x;
    int warp = threadIdx.x >> 5;
    int lane = threadIdx.x & 31;
    int line = blockIdx.y * 8 + warp;       // (i,j) line index, 0..80
    if (line >= 81) return;
    int i4 = line / 9, j4 = line % 9;
    int start = g_off[b], end = g_off[b + 1];

    const float* Pxr = g_phas[i4 * 2];
    const float* Pxi = g_phas[i4 * 2 + 1];
    const float* Pyr = g_phas[(9 + j4) * 2];
    const float* Pyi = g_phas[(9 + j4) * 2 + 1];

    float aC[9][4], aS[9][4];
    #pragma unroll
    for (int z = 0; z < 9; z++)
        #pragma unroll
        for (int c = 0; c < 4; c++) { aC[z][c] = 0.0f; aS[z][c] = 0.0f; }

    // ---- pass 1: structure factors for this line ----
    for (int a = start + lane; a < end; a += 32) {
        float cxr = Pxr[a], cxi = Pxi[a];
        float cyr = Pyr[a], cyi = Pyi[a];
        float c1r = cxr * cyr - cxi * cyi;
        float c1i = cxr * cyi + cxi * cyr;
        float4 sv = *(const float4*)(source + 4 * a);
        #pragma unroll
        for (int z = 0; z < 9; z++) {
            float zr = g_phas[(18 + z) * 2][a];
            float zi = g_phas[(18 + z) * 2 + 1][a];
            float cr = c1r * zr - c1i * zi;   // cos(2pi f.k)
            float ci = c1r * zi + c1i * zr;   // sin(2pi f.k)
            aC[z][0] = fmaf(sv.x, cr, aC[z][0]);
            aC[z][1] = fmaf(sv.y, cr, aC[z][1]);
            aC[z][2] = fmaf(sv.z, cr, aC[z][2]);
            aC[z][3] = fmaf(sv.w, cr, aC[z][3]);
            aS[z][0] = fmaf(sv.x, ci, aS[z][0]);
            aS[z][1] = fmaf(sv.y, ci, aS[z][1]);
            aS[z][2] = fmaf(sv.z, ci, aS[z][2]);
            aS[z][3] = fmaf(sv.w, ci, aS[z][3]);
        }
    }
    // butterfly reduce: every lane ends with the full sums
    #pragma unroll
    for (int z = 0; z < 9; z++)
        #pragma unroll
        for (int c = 0; c < 4; c++) {
            float v1 = aC[z][c], v2 = aS[z][c];
            #pragma unroll
            for (int o = 16; o; o >>= 1) {
                v1 += __shfl_xor_sync(0xffffffffu, v1, o);
                v2 += __shfl_xor_sync(0xffffffffu, v2, o);
            }
            aC[z][c] = v1; aS[z][c] = v2;
        }

    float wz[9];
    #pragma unroll
    for (int z = 0; z < 9; z++) wz[z] = g_w[b][line * 9 + z];
    float hv = 0.5f * g_vinv[b];

    // ---- pass 2: per-atom energy contribution from this line's 9 k's ----
    for (int a = start + lane; a < end; a += 32) {
        float cxr = Pxr[a], cxi = Pxi[a];
        float cyr = Pyr[a], cyi = Pyi[a];
        float c1r = cxr * cyr - cxi * cyi;
        float c1i = cxr * cyi + cxi * cyr;
        float4 sv = *(const float4*)(source + 4 * a);
        float e = 0.0f;
        #pragma unroll
        for (int z = 0; z < 9; z++) {
            float zr = g_phas[(18 + z) * 2][a];
            float zi = g_phas[(18 + z) * 2 + 1][a];
            float cr = c1r * zr - c1i * zi;
            float ci = c1r * zi + c1i * zr;
            float sc = sv.x * aC[z][0] + sv.y * aC[z][1] + sv.z * aC[z][2] + sv.w * aC[z][3];
            float ss = sv.x * aS[z][0] + sv.y * aS[z][1] + sv.z * aS[z][2] + sv.w * aS[z][3];
            e = fmaf(wz[z], fmaf(cr, sc, ci * ss), e);
        }
        atomicAdd(out + a, hv * e);
    }
}

// ---------------------------------------------------------------------------
extern "C" void kernel_launch(void* const* d_in, const int* in_sizes, int n_in,
                              void* d_out, int out_size)
{
    const float* pos    = (const float*)d_in[0];
    const int*   batch  = (const int*)d_in[1];
    const float* cell   = (const float*)d_in[2];
    const float* source = (const float*)d_in[3];
    const float* W1 = (const float*)d_in[4];
    const float* B1 = (const float*)d_in[5];
    const float* W2 = (const float*)d_in[6];
    const float* B2 = (const float*)d_in[7];
    const float* W3 = (const float*)d_in[8];
    const float* B3 = (const float*)d_in[9];
    float* out = (float*)d_out;

    k_setup  <<<1, 64>>>(cell, batch);
    k_phasors<<<(NN + 255) / 256, 256>>>(pos, batch, out);
    k_weights<<<(NB * NK + 127) / 128, 128>>>(W1, B1, W2, B2, W3, B3);
    k_main   <<<dim3(NB, 11), 256>>>(source, out);
}

// round 6
// speedup vs baseline: 1.0047x; 1.0047x over previous
#include <cuda_runtime.h>
#include <math.h>

// Problem constants (fixed by the dataset)
#define NN 8192          // atoms
#define NB 32            // graphs
#define NH 64            // hidden
#define NK 729           // 9^3 lattice points (k=0 kept with w=0)

#define TWO_PI  6.28318530717958647692f
#define FOUR_PI 12.5663706143591729539f

// -------- device scratch (no allocations allowed) --------
__device__ float g_inv[NB][9];      // inverse cells, row-major [d][h]
__device__ float g_vinv[NB];        // 1 / max(|det|, 1e-6)
__device__ int   g_off[NB + 1];     // batch segment offsets (batch is sorted)
__device__ float g_w[NB][NK];       // per-(graph,k) radial weight
// per-atom phasor table: row = (d*9 + (m+4))*2 + {re,im}, col = atom (coalesced)
__device__ float g_phas[54][NN];

// ---------------------------------------------------------------------------
// Kernel 0: 3x3 inverses (double precision) + volumes + batch offsets
// ---------------------------------------------------------------------------
__global__ void k_setup(const float* __restrict__ cell, const int* __restrict__ batch)
{
    int t = threadIdx.x;
    if (t < NB) {
        const float* c = cell + t * 9;
        double a = c[0], b = c[1], cc = c[2];
        double d = c[3], e = c[4], f  = c[5];
        double g = c[6], h = c[7], i  = c[8];
        double A  = e * i - f * h;
        double Bv = f * g - d * i;
        double C  = d * h - e * g;
        double det = a * A + b * Bv + cc * C;
        double vol = fabs(det);
        if (vol < 1e-6) vol = 1e-6;
        g_vinv[t] = (float)(1.0 / vol);
        double id = 1.0 / det;
        g_inv[t][0] = (float)(A * id);
        g_inv[t][1] = (float)((cc * h - b * i) * id);
        g_inv[t][2] = (float)((b * f - cc * e) * id);
        g_inv[t][3] = (float)(Bv * id);
        g_inv[t][4] = (float)((a * i - cc * g) * id);
        g_inv[t][5] = (float)((cc * d - a * f) * id);
        g_inv[t][6] = (float)(C * id);
        g_inv[t][7] = (float)((b * g - a * h) * id);
        g_inv[t][8] = (float)((a * e - b * d) * id);
    }
    if (t <= NB) {   // lower_bound(batch, t) — batch is sorted
        int lo = 0, hi = NN;
        while (lo < hi) {
            int mid = (lo + hi) >> 1;
            if (batch[mid] < t) lo = mid + 1; else hi = mid;
        }
        g_off[t] = lo;
    }
}

// ---------------------------------------------------------------------------
// Kernel 1: per-atom unit phasors e^{i*2pi*frac_d*m}, m=-4..4, d=0..2.
// Only 3 sincos per atom; powers built by complex multiplication.
// Also zero-initializes the (poisoned) output buffer.
// ---------------------------------------------------------------------------
__global__ void k_phasors(const float* __restrict__ pos, const int* __restrict__ batch,
                          float* __restrict__ out)
{
    int n = blockIdx.x * blockDim.x + threadIdx.x;
    if (n >= NN) return;
    out[n] = 0.0f;
    int b = batch[n];
    float px = pos[3 * n], py = pos[3 * n + 1], pz = pos[3 * n + 2];
    #pragma unroll
    for (int d = 0; d < 3; d++) {
        // frac[d] = sum_i pos[i] * inv[i][d]
        float fr = px * g_inv[b][d] + py * g_inv[b][3 + d] + pz * g_inv[b][6 + d];
        float th = TWO_PI * fr;
        float s, c;
        sincosf(th, &s, &c);
        float re[9], im[9];
        re[4] = 1.0f; im[4] = 0.0f;
        re[5] = c;    im[5] = s;
        #pragma unroll
        for (int m = 2; m <= 4; m++) {
            re[4 + m] = re[3 + m] * c - im[3 + m] * s;
            im[4 + m] = re[3 + m] * s + im[3 + m] * c;
        }
        #pragma unroll
        for (int m = 1; m <= 4; m++) { re[4 - m] = re[4 + m]; im[4 - m] = -im[4 + m]; }
        #pragma unroll
        for (int mi = 0; mi < 9; mi++) {
            g_phas[(d * 9 + mi) * 2 + 0][n] = re[mi];
            g_phas[(d * 9 + mi) * 2 + 1][n] = im[mi];
        }
    }
}

// ---------------------------------------------------------------------------
// Kernel 2: MLP radial filter -> g_w[b][k].  One thread per (b,k).
// W2 staged transposed in shared so the inner dot is contiguous.
// ---------------------------------------------------------------------------
__global__ void __launch_bounds__(128) k_weights(
    const float* __restrict__ W1, const float* __restrict__ B1,
    const float* __restrict__ W2, const float* __restrict__ B2,
    const float* __restrict__ W3, const float* __restrict__ B3)
{
    __shared__ float sW1[3 * NH], sB1[NH], sW2T[NH * NH], sB2[NH], sW3[NH];
    __shared__ float sInv[NB * 9];
    int tid = threadIdx.x;
    for (int idx = tid; idx < 3 * NH; idx += blockDim.x) sW1[idx] = W1[idx];
    for (int idx = tid; idx < NH; idx += blockDim.x) {
        sB1[idx] = B1[idx]; sB2[idx] = B2[idx]; sW3[idx] = W3[idx];
    }
    for (int idx = tid; idx < NH * NH; idx += blockDim.x) {
        int i = idx >> 6, j = idx & 63;
        sW2T[j * NH + i] = W2[idx];
    }
    for (int idx = tid; idx < NB * 9; idx += blockDim.x)
        sInv[idx] = (&g_inv[0][0])[idx];
    __syncthreads();

    int g = blockIdx.x * blockDim.x + tid;
    if (g >= NB * NK) return;
    int b = g / NK, k = g - b * NK;
    int ki = k / 81 - 4;
    int kj = (k / 9) % 9 - 4;
    int kk = k % 9 - 4;
    const float* iv = &sInv[b * 9];
    // k_cart[h] = 2pi * sum_d klat[d] * inv[d][h]
    float kc0 = TWO_PI * ((float)ki * iv[0] + (float)kj * iv[3] + (float)kk * iv[6]);
    float kc1 = TWO_PI * ((float)ki * iv[1] + (float)kj * iv[4] + (float)kk * iv[7]);
    float kc2 = TWO_PI * ((float)ki * iv[2] + (float)kj * iv[5] + (float)kk * iv[8]);
    float kn = sqrtf(kc0 * kc0 + kc1 * kc1 + kc2 * kc2);

    float w = 0.0f;
    if (kn > 1e-6f) {           // only k=0 fails this
        float x0 = log1pf(kn);
        float f0 = x0, f1 = x0 * x0, f2 = 1.0f / kn;
        float h1[NH];
        #pragma unroll
        for (int j = 0; j < NH; j++) {
            float a = fmaf(f0, sW1[j], fmaf(f1, sW1[NH + j], fmaf(f2, sW1[2 * NH + j], sB1[j])));
            h1[j] = a / (1.0f + __expf(-a));          // silu
        }
        float o = B3[0];
        for (int j = 0; j < NH; j++) {
            float a = sB2[j];
            #pragma unroll
            for (int i2 = 0; i2 < NH; i2++) a = fmaf(h1[i2], sW2T[j * NH + i2], a);
            float h2 = a / (1.0f + __expf(-a));        // silu
            o = fmaf(h2, sW3[j], o);
        }
        float sp = (o > 80.0f) ? o : log1pf(__expf(o));  // softplus
        w = (FOUR_PI / (kn * kn)) * sp;
    }
    g_w[b][k] = w;
}

// ---------------------------------------------------------------------------
// Kernel 3 (fused): warp owns (graph b, line (i,j)) -> 9 k's.
// Pass 1: accumulate S_cos/S_sin[9][4] over the graph's atoms (lane-strided),
//         butterfly reduce so every lane holds the totals.
// Pass 2: re-walk atoms (L1-hot), compute the 9-k energy contribution per atom,
//         atomicAdd into out[n].
// ---------------------------------------------------------------------------
__global__ void __launch_bounds__(256) k_main(const float* __restrict__ source,
                                              float* __restrict__ out)
{
    int b    = blockIdx.x;
    int warp = threadIdx.x >> 5;
    int lane = threadIdx.x & 31;
    int line = blockIdx.y * 8 + warp;       // (i,j) line index, 0..80
    if (line >= 81) return;
    int i4 = line / 9, j4 = line % 9;
    int start = g_off[b], end = g_off[b + 1];

    const float* Pxr = g_phas[i4 * 2];
    const float* Pxi = g_phas[i4 * 2 + 1];
    const float* Pyr = g_phas[(9 + j4) * 2];
    const float* Pyi = g_phas[(9 + j4) * 2 + 1];

    float aC[9][4], aS[9][4];
    #pragma unroll
    for (int z = 0; z < 9; z++)
        #pragma unroll
        for (int c = 0; c < 4; c++) { aC[z][c] = 0.0f; aS[z][c] = 0.0f; }

    // ---- pass 1: structure factors for this line ----
    for (int a = start + lane; a < end; a += 32) {
        float cxr = Pxr[a], cxi = Pxi[a];
        float cyr = Pyr[a], cyi = Pyi[a];
        float c1r = cxr * cyr - cxi * cyi;
        float c1i = cxr * cyi + cxi * cyr;
        float4 sv = *(const float4*)(source + 4 * a);
        #pragma unroll
        for (int z = 0; z < 9; z++) {
            float zr = g_phas[(18 + z) * 2][a];
            float zi = g_phas[(18 + z) * 2 + 1][a];
            float cr = c1r * zr - c1i * zi;   // cos(2pi f.k)
            float ci = c1r * zi + c1i * zr;   // sin(2pi f.k)
            aC[z][0] = fmaf(sv.x, cr, aC[z][0]);
            aC[z][1] = fmaf(sv.y, cr, aC[z][1]);
            aC[z][2] = fmaf(sv.z, cr, aC[z][2]);
            aC[z][3] = fmaf(sv.w, cr, aC[z][3]);
            aS[z][0] = fmaf(sv.x, ci, aS[z][0]);
            aS[z][1] = fmaf(sv.y, ci, aS[z][1]);
            aS[z][2] = fmaf(sv.z, ci, aS[z][2]);
            aS[z][3] = fmaf(sv.w, ci, aS[z][3]);
        }
    }
    // butterfly reduce: every lane ends with the full sums
    #pragma unroll
    for (int z = 0; z < 9; z++)
        #pragma unroll
        for (int c = 0; c < 4; c++) {
            float v1 = aC[z][c], v2 = aS[z][c];
            #pragma unroll
            for (int o = 16; o; o >>= 1) {
                v1 += __shfl_xor_sync(0xffffffffu, v1, o);
                v2 += __shfl_xor_sync(0xffffffffu, v2, o);
            }
            aC[z][c] = v1; aS[z][c] = v2;
        }

    float wz[9];
    #pragma unroll
    for (int z = 0; z < 9; z++) wz[z] = g_w[b][line * 9 + z];
    float hv = 0.5f * g_vinv[b];

    // ---- pass 2: per-atom energy contribution from this line's 9 k's ----
    for (int a = start + lane; a < end; a += 32) {
        float cxr = Pxr[a], cxi = Pxi[a];
        float cyr = Pyr[a], cyi = Pyi[a];
        float c1r = cxr * cyr - cxi * cyi;
        float c1i = cxr * cyi + cxi * cyr;
        float4 sv = *(const float4*)(source + 4 * a);
        float e = 0.0f;
        #pragma unroll
        for (int z = 0; z < 9; z++) {
            float zr = g_phas[(18 + z) * 2][a];
            float zi = g_phas[(18 + z) * 2 + 1][a];
            float cr = c1r * zr - c1i * zi;
            float ci = c1r * zi + c1i * zr;
            float sc = sv.x * aC[z][0] + sv.y * aC[z][1] + sv.z * aC[z][2] + sv.w * aC[z][3];
            float ss = sv.x * aS[z][0] + sv.y * aS[z][1] + sv.z * aS[z][2] + sv.w * aS[z][3];
            e = fmaf(wz[z], fmaf(cr, sc, ci * ss), e);
        }
        atomicAdd(out + a, hv * e);
    }
}

// ---------------------------------------------------------------------------
extern "C" void kernel_launch(void* const* d_in, const int* in_sizes, int n_in,
                              void* d_out, int out_size)
{
    const float* pos    = (const float*)d_in[0];
    const int*   batch  = (const int*)d_in[1];
    const float* cell   = (const float*)d_in[2];
    const float* source = (const float*)d_in[3];
    const float* W1 = (const float*)d_in[4];
    const float* B1 = (const float*)d_in[5];
    const float* W2 = (const float*)d_in[6];
    const float* B2 = (const float*)d_in[7];
    const float* W3 = (const float*)d_in[8];
    const float* B3 = (const float*)d_in[9];
    float* out = (float*)d_out;

    k_setup  <<<1, 64>>>(cell, batch);
    k_phasors<<<(NN + 255) / 256, 256>>>(pos, batch, out);
    k_weights<<<(NB * NK + 127) / 128, 128>>>(W1, B1, W2, B2, W3, B3);
    k_main   <<<dim3(NB, 11), 256>>>(source, out);
}